// round 13
// baseline (speedup 1.0000x reference)
#include <cuda_runtime.h>
#include <cuda_fp16.h>
#include <cuda_bf16.h>
#include <cstdint>

#define FEAT 128
#define FPL  2048
#define NMAX 50000
#define EMAX 600000
#define LOG2E 1.4426950408889634f

typedef unsigned long long u64;
typedef long long s64;

// ---------------- static device scratch ----------------
// fragment-layout exp scratch: [tile][chunk 32][warp 8][tp 4][lane 32] x uint4
__device__ __align__(16) uint4 g_Efrag[(size_t)392 * 32768];
__device__ float  g_agg[(size_t)NMAX * FEAT];  // aggregated features
__device__ float  g_h0[(size_t)NMAX * FEAT];   // hidden ping
__device__ float  g_h1[(size_t)NMAX * FEAT];   // hidden pong
__device__ int    g_rowptr[NMAX + 1];
__device__ int    g_cursor[NMAX];
__device__ int    g_col[EMAX];
__device__ float  g_stats[2 * FEAT];
__device__ float  g_bnAll[2][5][FEAT];         // [A|B][layer slot][chan]
__device__ int    g_mode32;
__device__ int    g_bsum[256];
// fp16 weights, n-major per 64-col chunk: 5 matrices x 32 chunks x (64 n x 128 k) = 16384B each
__device__ __align__(16) unsigned char g_Wbf[5 * 32 * 16384];
__device__ float  g_bsc[5 * FPL];              // biases pre-scaled by log2e

// ---------------- f32x2 helpers ----------------
__device__ __forceinline__ u64 pk2(float x) {
    u64 r; asm("mov.b64 %0,{%1,%1};" : "=l"(r) : "f"(x)); return r;
}
__device__ __forceinline__ u64 pack2f(float a, float b) {
    u64 r; asm("mov.b64 %0,{%1,%2};" : "=l"(r) : "f"(a), "f"(b)); return r;
}
__device__ __forceinline__ void fma2(u64& d, u64 a, u64 b) {
    asm("fma.rn.f32x2 %0,%1,%2,%0;" : "+l"(d) : "l"(a), "l"(b));
}
__device__ __forceinline__ u64 add2p(u64 a, u64 b) {
    u64 r; asm("add.rn.f32x2 %0,%1,%2;" : "=l"(r) : "l"(a), "l"(b)); return r;
}
__device__ __forceinline__ u64 fma2p(u64 a, u64 b, u64 c) {
    u64 r; asm("fma.rn.f32x2 %0,%1,%2,%3;" : "=l"(r) : "l"(a), "l"(b), "l"(c)); return r;
}
__device__ __forceinline__ float2 up2(u64 v) {
    float2 r; asm("mov.b64 {%0,%1},%2;" : "=f"(r.x), "=f"(r.y) : "l"(v)); return r;
}

// packed exp2 on a float pair (inputs <= 15.5; lower range safe to -126)
__device__ __forceinline__ u64 fexp2x2(u64 y) {
    u64 t = add2p(y, pk2(12582912.f));
    float2 tf = up2(t);
    int sh0 = __float_as_int(tf.x) << 23;
    int sh1 = __float_as_int(tf.y) << 23;
    u64 m = add2p(t, pk2(-12582912.f));                 // round(y)
    u64 f = add2p(y, m ^ 0x8000000080000000ULL);        // y - round(y), in [-0.5,0.5]
    u64 p = fma2p(pk2(0.0089893397f), f, pk2(0.055826318f));
    p = fma2p(p, f, pk2(0.24015361f));
    p = fma2p(p, f, pk2(0.69315168f));
    p = fma2p(p, f, pk2(1.0f));
    float2 pf = up2(p);
    return pack2f(__int_as_float(__float_as_int(pf.x) + sh0),
                  __int_as_float(__float_as_int(pf.y) + sh1));
}
__device__ __forceinline__ uint32_t h2of(u64 e) {
    float2 f = up2(e);
    __half2 h = __floats2half2_rn(f.x, f.y);
    return *(uint32_t*)&h;
}

// ---------------- mma.sync helpers (base PTX, sm_80+) ----------------
__device__ __forceinline__ uint32_t smem_u32(const void* p) {
    uint32_t a;
    asm("{ .reg .u64 t; cvta.to.shared.u64 t, %1; cvt.u32.u64 %0, t; }" : "=r"(a) : "l"(p));
    return a;
}
__device__ __forceinline__ void ldm_x4(uint32_t& a0, uint32_t& a1, uint32_t& a2, uint32_t& a3, uint32_t addr) {
    asm volatile("ldmatrix.sync.aligned.m8n8.x4.shared.b16 {%0,%1,%2,%3}, [%4];"
                 : "=r"(a0), "=r"(a1), "=r"(a2), "=r"(a3) : "r"(addr));
}
// fp16 in / fp16 accumulate — 2x rate vs f32 accum
__device__ __forceinline__ void mma16816h(uint32_t* c, uint32_t a0, uint32_t a1, uint32_t a2, uint32_t a3,
                                          uint32_t b0, uint32_t b1) {
    asm volatile("mma.sync.aligned.m16n8k16.row.col.f16.f16.f16.f16 "
                 "{%0,%1}, {%2,%3,%4,%5}, {%6,%7}, {%0,%1};"
                 : "+r"(c[0]), "+r"(c[1])
                 : "r"(a0), "r"(a1), "r"(a2), "r"(a3), "r"(b0), "r"(b1));
}

#define CP_ASYNC16(dst, src) asm volatile("cp.async.cg.shared.global [%0], [%1], 16;" :: "r"(dst), "l"(src))
#define CP_COMMIT()          asm volatile("cp.async.commit_group;" ::: "memory")
#define CP_WAIT2()           asm volatile("cp.async.wait_group 2;" ::: "memory")

// ---------------- init / graph preprocessing ----------------
__global__ void init_kernel(float* __restrict__ out, int nrows) {
    int i = blockIdx.x * blockDim.x + threadIdx.x;
    if (i < nrows) g_cursor[i] = 0;
    if (i < FPL) out[i] = 0.f;
    if (i < FEAT) { g_bnAll[0][0][i] = 1.f; g_bnAll[1][0][i] = 0.f; }
    if (i == 0) g_mode32 = 0;
}

__global__ void probe_kernel(const s64* __restrict__ ei, int nedges, int nrows) {
    int t = threadIdx.x;
    if (t < nedges && t < 1024) {
        s64 v = ei[t];
        if (v < 0 || v >= (s64)nrows) atomicExch(&g_mode32, 1);
    }
}

__global__ void hist_kernel(const s64* __restrict__ ei, int nedges) {
    int e = blockIdx.x * blockDim.x + threadIdx.x;
    if (e >= nedges) return;
    int d = g_mode32 ? ((const int*)ei)[nedges + e] : (int)ei[nedges + e];
    atomicAdd(&g_cursor[d], 1);
}

__global__ void scanA_kernel(int n) {
    __shared__ int sred[256];
    int b = blockIdx.x, t = threadIdx.x, i = b * 256 + t;
    sred[t] = (i < n) ? g_cursor[i] : 0;
    __syncthreads();
    for (int o = 128; o > 0; o >>= 1) {
        if (t < o) sred[t] += sred[t + o];
        __syncthreads();
    }
    if (t == 0) g_bsum[b] = sred[0];
}
__global__ void scanB_kernel(int nblk, int n, int E) {
    __shared__ int ss[256];
    int t = threadIdx.x;
    int v = (t < nblk) ? g_bsum[t] : 0;
    ss[t] = v; __syncthreads();
    for (int o = 1; o < 256; o <<= 1) {
        int u = (t >= o) ? ss[t - o] : 0;
        __syncthreads(); ss[t] += u; __syncthreads();
    }
    if (t < nblk) g_bsum[t] = ss[t] - v;   // exclusive
    if (t == 0) g_rowptr[n] = E;
}
__global__ void scanC_kernel(int n) {
    __shared__ int ss[256];
    int b = blockIdx.x, t = threadIdx.x, i = b * 256 + t;
    int v = (i < n) ? g_cursor[i] : 0;
    ss[t] = v; __syncthreads();
    for (int o = 1; o < 256; o <<= 1) {
        int u = (t >= o) ? ss[t - o] : 0;
        __syncthreads(); ss[t] += u; __syncthreads();
    }
    if (i < n) {
        int p = g_bsum[b] + ss[t] - v;
        g_rowptr[i] = p;
        g_cursor[i] = p;
    }
}

__global__ void fill_kernel(const s64* __restrict__ ei, int nedges) {
    int e = blockIdx.x * blockDim.x + threadIdx.x;
    if (e >= nedges) return;
    int d, sv;
    if (g_mode32) {
        const int* p = (const int*)ei;
        sv = p[e]; d = p[nedges + e];
    } else {
        sv = (int)ei[e]; d = (int)ei[nedges + e];
    }
    int pos = atomicAdd(&g_cursor[d], 1);
    g_col[pos] = sv;
}

// ---------------- weight conversion: fp32 [K][N] -> fp16 [n][k] per chunk, x log2e ----------------
__global__ void wconv_kernel(const float* __restrict__ init_w, const float* __restrict__ soft_w) {
    __shared__ __align__(16) __half sbuf[64 * 128];
    int m = blockIdx.x >> 5, c = blockIdx.x & 31;
    const float* W = (m == 0) ? init_w : soft_w + (size_t)(m - 1) * FEAT * FPL;
    for (int i = threadIdx.x; i < 64 * 128; i += 256) {
        int nn = i & 63, k = i >> 6;
        float v = W[(size_t)k * FPL + c * 64 + nn] * LOG2E;
        sbuf[nn * 128 + k] = __float2half_rn(v);
    }
    __syncthreads();
    uint4* dst = (uint4*)(g_Wbf + ((size_t)m * 32 + c) * 16384);
    const uint4* src = (const uint4*)sbuf;
    for (int i = threadIdx.x; i < 1024; i += 256) dst[i] = src[i];
}

__global__ void bconv_kernel(const float* __restrict__ init_b, const float* __restrict__ soft_b) {
    int i = blockIdx.x * blockDim.x + threadIdx.x;
    if (i >= 5 * FPL) return;
    int m = i >> 11, j = i & 2047;
    float v = (m == 0) ? init_b[j] : soft_b[(m - 1) * FPL + j];
    g_bsc[i] = v * LOG2E;
}

// ---------------- aggregation: agg = A .* (self + sum_neigh) + B * cnt ----------------
// srcsel: 0 = Xext (atoms), 1 = g_h0, 2 = g_h1
__global__ void agg_kernel(const float* __restrict__ Xext, int srcsel, int bnslot, int nrows) {
    if (blockIdx.x == 0 && threadIdx.x < 2 * FEAT) g_stats[threadIdx.x] = 0.f;
    int w = (blockIdx.x * blockDim.x + threadIdx.x) >> 5;
    int lane = threadIdx.x & 31;
    if (w >= nrows) return;
    const float4* F = (srcsel == 0) ? (const float4*)Xext
                    : (srcsel == 1) ? (const float4*)g_h0 : (const float4*)g_h1;
    float4 A4 = ((const float4*)g_bnAll[0][bnslot])[lane];
    float4 B4 = ((const float4*)g_bnAll[1][bnslot])[lane];
    float4 a = F[(size_t)w * 32 + lane];
    int beg = g_rowptr[w], end = g_rowptr[w + 1];
    float cnt = (float)(end - beg + 1);
    for (int e = beg; e < end; e++) {
        float4 bb = __ldg(&F[(size_t)g_col[e] * 32 + lane]);
        a.x += bb.x; a.y += bb.y; a.z += bb.z; a.w += bb.w;
    }
    a.x = a.x * A4.x + B4.x * cnt;
    a.y = a.y * A4.y + B4.y * cnt;
    a.z = a.z * A4.z + B4.z * cnt;
    a.w = a.w * A4.w + B4.w * cnt;
    ((float4*)g_agg)[(size_t)w * 32 + lane] = a;
}

// ---------------- hash layer (fp32 FFMA2) ----------------
__global__ void __launch_bounds__(256, 2)
hash_kernel(const float* __restrict__ W, const float* __restrict__ bias, int dstsel, int nrows) {
    extern __shared__ float sm[];
    float* xs = sm;              // [128 k][64 r]
    float* ws = sm + FEAT * 64;  // [128 k][128 c]
    __shared__ float sstat[FEAT], ssq[FEAT];
    float* H = dstsel ? g_h1 : g_h0;
    int tid = threadIdx.x;
    int tj = tid & 15, ti = tid >> 4;
    int row0 = blockIdx.x * 64;
    if (tid < FEAT) { sstat[tid] = 0.f; ssq[tid] = 0.f; }

#pragma unroll
    for (int i = 0; i < 8; i++) {
        int idx = tid + i * 256;
        int r = idx >> 5, k4 = idx & 31;
        float4 v = make_float4(0.f, 0.f, 0.f, 0.f);
        if (row0 + r < nrows)
            v = *(const float4*)(g_agg + (size_t)(row0 + r) * FEAT + k4 * 4);
        xs[(k4 * 4 + 0) * 64 + r] = v.x;
        xs[(k4 * 4 + 1) * 64 + r] = v.y;
        xs[(k4 * 4 + 2) * 64 + r] = v.z;
        xs[(k4 * 4 + 3) * 64 + r] = v.w;
    }
#pragma unroll
    for (int i = 0; i < 16; i++) {
        int idx = tid + i * 256;
        *(float4*)(ws + idx * 4) = *(const float4*)(W + idx * 4);
    }
    __syncthreads();

    u64 acc[4][4];
#pragma unroll
    for (int r = 0; r < 4; r++)
#pragma unroll
        for (int c = 0; c < 4; c++) acc[r][c] = 0ull;

#pragma unroll 4
    for (int k = 0; k < FEAT; k++) {
        float4 xf = *(const float4*)(xs + k * 64 + ti * 4);
        ulonglong2 wa = *(const ulonglong2*)(ws + k * FEAT + tj * 8);
        ulonglong2 wb = *(const ulonglong2*)(ws + k * FEAT + tj * 8 + 4);
        u64 x0 = pk2(xf.x), x1 = pk2(xf.y), x2 = pk2(xf.z), x3 = pk2(xf.w);
        fma2(acc[0][0], x0, wa.x); fma2(acc[0][1], x0, wa.y); fma2(acc[0][2], x0, wb.x); fma2(acc[0][3], x0, wb.y);
        fma2(acc[1][0], x1, wa.x); fma2(acc[1][1], x1, wa.y); fma2(acc[1][2], x1, wb.x); fma2(acc[1][3], x1, wb.y);
        fma2(acc[2][0], x2, wa.x); fma2(acc[2][1], x2, wa.y); fma2(acc[2][2], x2, wb.x); fma2(acc[2][3], x2, wb.y);
        fma2(acc[3][0], x3, wa.x); fma2(acc[3][1], x3, wa.y); fma2(acc[3][2], x3, wb.x); fma2(acc[3][3], x3, wb.y);
    }

    int colb = tj * 8;
    float4 bv0 = *(const float4*)(bias + colb);
    float4 bv1 = *(const float4*)(bias + colb + 4);
    float bvals[8] = {bv0.x, bv0.y, bv0.z, bv0.w, bv1.x, bv1.y, bv1.z, bv1.w};
    float s[8], q[8];
#pragma unroll
    for (int j = 0; j < 8; j++) { s[j] = 0.f; q[j] = 0.f; }
#pragma unroll
    for (int rr = 0; rr < 4; rr++) {
        int row = row0 + ti * 4 + rr;
        if (row >= nrows) break;
        float hv[8];
#pragma unroll
        for (int cp = 0; cp < 4; cp++) {
            float2 f = up2(acc[rr][cp]);
            hv[2 * cp]     = fmaxf(f.x + bvals[2 * cp], 0.f);
            hv[2 * cp + 1] = fmaxf(f.y + bvals[2 * cp + 1], 0.f);
        }
        *(float4*)(H + (size_t)row * FEAT + colb)     = make_float4(hv[0], hv[1], hv[2], hv[3]);
        *(float4*)(H + (size_t)row * FEAT + colb + 4) = make_float4(hv[4], hv[5], hv[6], hv[7]);
#pragma unroll
        for (int j = 0; j < 8; j++) { s[j] += hv[j]; q[j] += hv[j] * hv[j]; }
    }
    __syncthreads();
#pragma unroll
    for (int j = 0; j < 8; j++) {
        atomicAdd(&sstat[colb + j], s[j]);
        atomicAdd(&ssq[colb + j], q[j]);
    }
    __syncthreads();
    if (tid < FEAT) {
        atomicAdd(&g_stats[tid], sstat[tid]);
        atomicAdd(&g_stats[FEAT + tid], ssq[tid]);
    }
}

__global__ void bnfinal_kernel(const float* __restrict__ gamma, const float* __restrict__ beta,
                               int nrows, int slot) {
    int c = threadIdx.x;
    float n = (float)nrows;
    float mu = g_stats[c] / n;
    float var = g_stats[FEAT + c] / n - mu * mu;
    float A = gamma[c] * rsqrtf(var + 1e-5f);
    g_bnAll[0][slot][c] = A;
    g_bnAll[1][slot][c] = beta[c] - mu * A;
}

// ---------------- HMMA softmax-GEMM (fp16 accum, fused pass 2, fragment scratch) ----------------
#define APITCH 136
#define ASZ (128 * APITCH * 2)   // 34816 bytes
#define BSZ (64 * APITCH * 2)    // 17408 bytes
#define SMEMB (ASZ + 4 * BSZ)    // 104448 bytes

__global__ void __launch_bounds__(256, 2)
softgemm_mma_kernel(const float* __restrict__ Xext, int xsel, int bnslot, int mIdx,
                    float* __restrict__ fp, int nrows) {
    extern __shared__ __align__(16) unsigned char dsm[];
    __shared__ __align__(16) float s_bias[4][64];
    __shared__ float s_sinv[128];
    __shared__ float s_bnA[FEAT], s_bnB[FEAT];

    const float* X = (xsel == 0) ? Xext : (xsel == 1 ? g_h0 : g_h1);
    int tid = threadIdx.x;
    int lane = tid & 31;
    int w = tid >> 5;            // warp 0..7
    int wr = w * 16;             // warp row base
    int row0 = blockIdx.x * 128;
    uint4* Et = g_Efrag + (size_t)blockIdx.x * 32768;   // this block's tile

    unsigned char* As = dsm;
    uint32_t As_u = smem_u32(As);
    uint32_t Bs_u[4] = { smem_u32(dsm + ASZ), smem_u32(dsm + ASZ + BSZ),
                         smem_u32(dsm + ASZ + 2 * BSZ), smem_u32(dsm + ASZ + 3 * BSZ) };
    uint32_t bias_u = smem_u32(s_bias);

    if (tid < FEAT) { s_bnA[tid] = g_bnAll[0][bnslot][tid]; s_bnB[tid] = g_bnAll[1][bnslot][tid]; }
    __syncthreads();   // bn coefficients visible

    const unsigned char* Wbase = g_Wbf + (size_t)mIdx * 32 * 16384;
    const float* bias = g_bsc + (size_t)mIdx * FPL;

    // ---- issue cp.async for chunks 0,1,2 ----
#pragma unroll
    for (int pc = 0; pc < 3; pc++) {
        const unsigned char* src = Wbase + (size_t)pc * 16384;
#pragma unroll
        for (int i = 0; i < 4; i++) {
            int idx = tid + i * 256;
            uint32_t dst = Bs_u[pc] + (uint32_t)((idx >> 4) * (APITCH * 2) + (idx & 15) * 16);
            CP_ASYNC16(dst, src + idx * 16);
        }
        if (tid < 16) CP_ASYNC16(bias_u + pc * 256 + tid * 16, (const unsigned char*)(bias + pc * 64) + tid * 16);
        CP_COMMIT();
    }

    // ---- stage A (fp16): thread t: row t>>1, k-half (t&1)*64 ----
    {
        int r = tid >> 1, kh = (tid & 1) * 64;
        bool v = (row0 + r) < nrows;
        const float* xr = X + (size_t)(row0 + r) * FEAT + kh;
        __half2* arow = (__half2*)(As + (r * APITCH + kh) * 2);
#pragma unroll 8
        for (int k = 0; k < 64; k += 2) {
            float v0 = 0.f, v1 = 0.f;
            if (v) {
                float2 xv = *(const float2*)(xr + k);
                v0 = xv.x * s_bnA[kh + k] + s_bnB[kh + k];
                v1 = xv.y * s_bnA[kh + k + 1] + s_bnB[kh + k + 1];
            }
            arow[k >> 1] = __floats2half2_rn(v0, v1);
        }
    }
    __syncthreads();   // A visible

    // ---- hoist A fragments for the whole block tile (fixed across chunks) ----
    int mi = lane >> 3;
    uint32_t a_base = As_u + (uint32_t)((wr + (mi & 1) * 8 + (lane & 7)) * (APITCH * 2) + (mi >> 1) * 16);
    uint32_t afr[8][4];
#pragma unroll
    for (int ks = 0; ks < 8; ks++)
        ldm_x4(afr[ks][0], afr[ks][1], afr[ks][2], afr[ks][3], a_base + ks * 32);

    // B ldmatrix x4 per-thread address: two n8 tiles at once
    int b_row = (lane & 7) + ((lane >> 4) << 3);      // 0..15
    int b_koff = ((lane >> 3) & 1) * 16;
    uint32_t b_off = (uint32_t)(b_row * (APITCH * 2) + b_koff);

    int gr0 = wr + (lane >> 2);
    bool r0v = (row0 + gr0) < nrows;
    bool r1v = (row0 + gr0 + 8) < nrows;
    int cq = (lane & 3) * 2;

    u64 rs0p = 0ull, rs1p = 0ull;   // packed f32x2 rowsums

    for (int c = 0; c < 32; c++) {
        int buf = c & 3;
        CP_WAIT2();
        __syncthreads();           // Bs[buf] + s_bias[buf] ready; also all warps done with buf (c-1)&3

        // prefetch chunk c+3 into buffer (c+3)&3 (its last reader finished at iter c-1)
        if (c + 3 < 32) {
            int pbuf = (c + 3) & 3;
            const unsigned char* src = Wbase + (size_t)(c + 3) * 16384;
#pragma unroll
            for (int i = 0; i < 4; i++) {
                int idx = tid + i * 256;
                uint32_t dst = Bs_u[pbuf] + (uint32_t)((idx >> 4) * (APITCH * 2) + (idx & 15) * 16);
                CP_ASYNC16(dst, src + idx * 16);
            }
            if (tid < 16) CP_ASYNC16(bias_u + pbuf * 256 + tid * 16,
                                     (const unsigned char*)(bias + (c + 3) * 64) + tid * 16);
        }
        CP_COMMIT();               // uniform commit (possibly empty group)

        uint32_t bb = Bs_u[buf] + b_off;
#pragma unroll
        for (int tp = 0; tp < 4; tp++) {
            uint32_t accA[2] = {0u, 0u};   // half2: [0]={c0,c1}@row gr0, [1]=@row gr0+8
            uint32_t accB[2] = {0u, 0u};
            uint32_t bt = bb + tp * 16 * (APITCH * 2);
#pragma unroll
            for (int ks = 0; ks < 8; ks++) {
                uint32_t b0, b1, b2, b3;
                ldm_x4(b0, b1, b2, b3, bt + ks * 32);
                mma16816h(accA, afr[ks][0], afr[ks][1], afr[ks][2], afr[ks][3], b0, b1);
                mma16816h(accB, afr[ks][0], afr[ks][1], afr[ks][2], afr[ks][3], b2, b3);
            }
            // epilogue — unpack f16 accum, packed bias add, scalar upper clamp, packed exp2
            u64 bpA = *(const u64*)(&s_bias[buf][2 * tp * 8 + cq]);
            u64 bpB = *(const u64*)(&s_bias[buf][(2 * tp + 1) * 8 + cq]);
            float2 fA0 = __half22float2(*(__half2*)&accA[0]);   // row gr0
            float2 fA1 = __half22float2(*(__half2*)&accA[1]);   // row gr0+8
            float2 fB0 = __half22float2(*(__half2*)&accB[0]);
            float2 fB1 = __half22float2(*(__half2*)&accB[1]);
            u64 sA_rA = add2p(pack2f(fA0.x, fA0.y), bpA);
            u64 sA_rB = add2p(pack2f(fA1.x, fA1.y), bpA);
            u64 sB_rA = add2p(pack2f(fB0.x, fB0.y), bpB);
            u64 sB_rB = add2p(pack2f(fB1.x, fB1.y), bpB);
            float2 t0 = up2(sA_rA), t1 = up2(sB_rA), t2 = up2(sA_rB), t3 = up2(sB_rB);
            u64 eA_rA = fexp2x2(pack2f(fminf(t0.x, 15.5f), fminf(t0.y, 15.5f)));
            u64 eB_rA = fexp2x2(pack2f(fminf(t1.x, 15.5f), fminf(t1.y, 15.5f)));
            u64 eA_rB = fexp2x2(pack2f(fminf(t2.x, 15.5f), fminf(t2.y, 15.5f)));
            u64 eB_rB = fexp2x2(pack2f(fminf(t3.x, 15.5f), fminf(t3.y, 15.5f)));
            rs0p = add2p(add2p(rs0p, eA_rA), eB_rA);
            rs1p = add2p(add2p(rs1p, eA_rB), eB_rB);
            uint4 ov;
            ov.x = h2of(eA_rA); ov.y = h2of(eB_rA);
            ov.z = h2of(eA_rB); ov.w = h2of(eB_rB);
            Et[((c * 8 + w) * 4 + tp) * 32 + lane] = ov;
        }
    }

    // rowsum: horizontal add of packed halves, reduce across the 4 lanes sharing a row
    float2 r0f = up2(rs0p), r1f = up2(rs1p);
    float rs0 = r0f.x + r0f.y;
    float rs1 = r1f.x + r1f.y;
#pragma unroll
    for (int o = 1; o < 4; o <<= 1) {
        rs0 += __shfl_xor_sync(0xFFFFFFFFu, rs0, o);
        rs1 += __shfl_xor_sync(0xFFFFFFFFu, rs1, o);
    }
    if ((lane & 3) == 0) {
        s_sinv[gr0] = r0v ? (1.0f / rs0) : 0.f;
        s_sinv[gr0 + 8] = r1v ? (1.0f / rs1) : 0.f;
    }
    __syncthreads();   // stores + s_sinv visible block-wide

    // ---- fused pass 2: walk fragment layout, normalize, column-reduce into fp ----
    {
        int c8 = tid >> 3;                 // chunk 0..31
        int sub = tid & 7;
        int tp2 = sub >> 1, lqh = sub & 1;
        float ca[8];
#pragma unroll
        for (int j = 0; j < 8; j++) ca[j] = 0.f;
        for (int w2 = 0; w2 < 8; w2++) {
#pragma unroll 2
            for (int lr = 0; lr < 8; lr++) {
                float inv0 = s_sinv[w2 * 16 + lr];
                float inv1 = s_sinv[w2 * 16 + lr + 8];
#pragma unroll
                for (int lql = 0; lql < 2; lql++) {
                    int lane2 = lr * 4 + 2 * lqh + lql;
                    uint4 v = Et[((c8 * 8 + w2) * 4 + tp2) * 32 + lane2];
                    const __half2* hh = (const __half2*)&v;
                    float2 f0 = __half22float2(hh[0]);
                    float2 f1 = __half22float2(hh[1]);
                    float2 f2 = __half22float2(hh[2]);
                    float2 f3 = __half22float2(hh[3]);
                    ca[lql * 4 + 0] += f0.x * inv0 + f2.x * inv1;
                    ca[lql * 4 + 1] += f0.y * inv0 + f2.y * inv1;
                    ca[lql * 4 + 2] += f1.x * inv0 + f3.x * inv1;
                    ca[lql * 4 + 3] += f1.y * inv0 + f3.y * inv1;
                }
            }
        }
        int base = c8 * 64 + 16 * tp2;
#pragma unroll
        for (int lql = 0; lql < 2; lql++) {
            int lq = 2 * lqh + lql;
            atomicAdd(&fp[base + 2 * lq],         ca[lql * 4 + 0]);
            atomicAdd(&fp[base + 2 * lq + 1],     ca[lql * 4 + 1]);
            atomicAdd(&fp[base + 8 + 2 * lq],     ca[lql * 4 + 2]);
            atomicAdd(&fp[base + 8 + 2 * lq + 1], ca[lql * 4 + 3]);
        }
    }
}

// ---------------- launch ----------------
extern "C" void kernel_launch(void* const* d_in, const int* in_sizes, int n_in,
                              void* d_out, int out_size) {
    const float* atoms  = (const float*)d_in[0];
    const s64*   ei     = (const s64*)d_in[1];
    const float* init_w = (const float*)d_in[2];
    const float* init_b = (const float*)d_in[3];
    const float* hash_w = (const float*)d_in[4];
    const float* hash_b = (const float*)d_in[5];
    const float* soft_w = (const float*)d_in[6];
    const float* soft_b = (const float*)d_in[7];
    const float* gamma  = (const float*)d_in[8];
    const float* beta   = (const float*)d_in[9];
    float* out = (float*)d_out;

    int n = in_sizes[0] / FEAT;
    int E = in_sizes[1] / 2;
    int gb64 = (n + 63) / 64;
    int gb128 = (n + 127) / 128;
    int nscan = (n + 255) / 256;

    // one-time resources (host-side only; no device allocations)
    static cudaStream_t sB = nullptr;
    static cudaEvent_t evR[5], evS[5];
    if (sB == nullptr) {
        cudaStreamCreateWithFlags(&sB, cudaStreamNonBlocking);
        for (int i = 0; i < 5; i++) {
            cudaEventCreateWithFlags(&evR[i], cudaEventDisableTiming);
            cudaEventCreateWithFlags(&evS[i], cudaEventDisableTiming);
        }
    }

    cudaFuncSetAttribute(hash_kernel, cudaFuncAttributeMaxDynamicSharedMemorySize, 98304);
    cudaFuncSetAttribute(softgemm_mma_kernel, cudaFuncAttributeMaxDynamicSharedMemorySize, SMEMB);

    // ---- stream A (default): only what softgemm0 needs, then fork early ----
    init_kernel<<<(n + 255) / 256, 256>>>(out, n);
    probe_kernel<<<1, 1024>>>(ei, E, n);
    wconv_kernel<<<5 * 32, 256>>>(init_w, soft_w);
    bconv_kernel<<<(5 * FPL + 255) / 256, 256>>>(init_b, soft_b);

    // fork: softgemm 0 on stream B (doesn't need the CSR)
    cudaEventRecord(evR[0], (cudaStream_t)0);
    cudaStreamWaitEvent(sB, evR[0], 0);
    softgemm_mma_kernel<<<gb128, 256, SMEMB, sB>>>(atoms, 0, 0, 0, out, n);
    cudaEventRecord(evS[0], sB);

    // ---- stream A: build CSR concurrent with softgemm 0 ----
    hist_kernel<<<(E + 255) / 256, 256>>>(ei, E);
    scanA_kernel<<<nscan, 256>>>(n);
    scanB_kernel<<<1, 256>>>(nscan, n, E);
    scanC_kernel<<<nscan, 256>>>(n);
    fill_kernel<<<(E + 255) / 256, 256>>>(ei, E);

    // layers i = 1..4: chain on stream A runs concurrent with softgemm_{i-1} on stream B
    for (int i = 1; i <= 4; i++) {
        int srcsel = (i == 1) ? 0 : (((i - 1) & 1) + 1);
        agg_kernel<<<(n * 32 + 255) / 256, 256>>>(atoms, srcsel, i - 1, n);
        // hash_i writes h[i&1], which softgemm_{i-2} read — fence that WAR
        if (i >= 3) cudaStreamWaitEvent((cudaStream_t)0, evS[i - 2], 0);
        hash_kernel<<<gb64, 256, 98304>>>(hash_w + (size_t)(i - 1) * FEAT * FEAT,
                                          hash_b + (size_t)(i - 1) * FEAT, i & 1, n);
        bnfinal_kernel<<<1, FEAT>>>(gamma, beta, n, i);
        cudaEventRecord(evR[i], (cudaStream_t)0);
        cudaStreamWaitEvent(sB, evR[i], 0);
        softgemm_mma_kernel<<<gb128, 256, SMEMB, sB>>>(nullptr, (i & 1) + 1, i, i, out, n);
        cudaEventRecord(evS[i], sB);
    }

    // join stream B back into the default stream
    cudaStreamWaitEvent((cudaStream_t)0, evS[4], 0);
}

// round 14
// speedup vs baseline: 1.0164x; 1.0164x over previous
#include <cuda_runtime.h>
#include <cuda_fp16.h>
#include <cuda_bf16.h>
#include <cstdint>

#define FEAT 128
#define FPL  2048
#define NMAX 50000
#define EMAX 600000
#define LOG2E 1.4426950408889634f

typedef unsigned long long u64;
typedef long long s64;

// ---------------- static device scratch ----------------
// fragment-layout exp scratch: [tile][chunk 32][warp 8][tp 4][lane 32] x uint4
__device__ __align__(16) uint4 g_Efrag[(size_t)392 * 32768];
__device__ float  g_agg[(size_t)NMAX * FEAT];  // aggregated features
__device__ float  g_h0[(size_t)NMAX * FEAT];   // hidden ping
__device__ float  g_h1[(size_t)NMAX * FEAT];   // hidden pong
__device__ int    g_rowptr[NMAX + 1];
__device__ int    g_cursor[NMAX];
__device__ int    g_col[EMAX];
__device__ float  g_stats[2 * FEAT];
__device__ float  g_bnAll[2][5][FEAT];         // [A|B][layer slot][chan]
__device__ int    g_mode32;
__device__ int    g_bsum[256];
// fp16 weights, n-major per 64-col chunk: 5 matrices x 32 chunks x (64 n x 128 k) = 16384B each
__device__ __align__(16) unsigned char g_Wbf[5 * 32 * 16384];
__device__ float  g_bsc[5 * FPL];              // biases pre-scaled by log2e

// ---------------- f32x2 helpers ----------------
__device__ __forceinline__ u64 pk2(float x) {
    u64 r; asm("mov.b64 %0,{%1,%1};" : "=l"(r) : "f"(x)); return r;
}
__device__ __forceinline__ u64 pack2f(float a, float b) {
    u64 r; asm("mov.b64 %0,{%1,%2};" : "=l"(r) : "f"(a), "f"(b)); return r;
}
__device__ __forceinline__ void fma2(u64& d, u64 a, u64 b) {
    asm("fma.rn.f32x2 %0,%1,%2,%0;" : "+l"(d) : "l"(a), "l"(b));
}
__device__ __forceinline__ u64 add2p(u64 a, u64 b) {
    u64 r; asm("add.rn.f32x2 %0,%1,%2;" : "=l"(r) : "l"(a), "l"(b)); return r;
}
__device__ __forceinline__ u64 fma2p(u64 a, u64 b, u64 c) {
    u64 r; asm("fma.rn.f32x2 %0,%1,%2,%3;" : "=l"(r) : "l"(a), "l"(b), "l"(c)); return r;
}
__device__ __forceinline__ float2 up2(u64 v) {
    float2 r; asm("mov.b64 {%0,%1},%2;" : "=f"(r.x), "=f"(r.y) : "l"(v)); return r;
}

// packed exp2 on a float pair (inputs <= 15.5; lower range safe to -126)
__device__ __forceinline__ u64 fexp2x2(u64 y) {
    u64 t = add2p(y, pk2(12582912.f));
    float2 tf = up2(t);
    int sh0 = __float_as_int(tf.x) << 23;
    int sh1 = __float_as_int(tf.y) << 23;
    u64 m = add2p(t, pk2(-12582912.f));                 // round(y)
    u64 f = add2p(y, m ^ 0x8000000080000000ULL);        // y - round(y), in [-0.5,0.5]
    u64 p = fma2p(pk2(0.0089893397f), f, pk2(0.055826318f));
    p = fma2p(p, f, pk2(0.24015361f));
    p = fma2p(p, f, pk2(0.69315168f));
    p = fma2p(p, f, pk2(1.0f));
    float2 pf = up2(p);
    return pack2f(__int_as_float(__float_as_int(pf.x) + sh0),
                  __int_as_float(__float_as_int(pf.y) + sh1));
}
__device__ __forceinline__ uint32_t h2of(u64 e) {
    float2 f = up2(e);
    __half2 h = __floats2half2_rn(f.x, f.y);
    return *(uint32_t*)&h;
}

// ---------------- mma.sync helpers (base PTX, sm_80+) ----------------
__device__ __forceinline__ uint32_t smem_u32(const void* p) {
    uint32_t a;
    asm("{ .reg .u64 t; cvta.to.shared.u64 t, %1; cvt.u32.u64 %0, t; }" : "=r"(a) : "l"(p));
    return a;
}
__device__ __forceinline__ void ldm_x4(uint32_t& a0, uint32_t& a1, uint32_t& a2, uint32_t& a3, uint32_t addr) {
    asm volatile("ldmatrix.sync.aligned.m8n8.x4.shared.b16 {%0,%1,%2,%3}, [%4];"
                 : "=r"(a0), "=r"(a1), "=r"(a2), "=r"(a3) : "r"(addr));
}
// fp16 in / fp16 accumulate
__device__ __forceinline__ void mma16816h(uint32_t* c, uint32_t a0, uint32_t a1, uint32_t a2, uint32_t a3,
                                          uint32_t b0, uint32_t b1) {
    asm volatile("mma.sync.aligned.m16n8k16.row.col.f16.f16.f16.f16 "
                 "{%0,%1}, {%2,%3,%4,%5}, {%6,%7}, {%0,%1};"
                 : "+r"(c[0]), "+r"(c[1])
                 : "r"(a0), "r"(a1), "r"(a2), "r"(a3), "r"(b0), "r"(b1));
}

#define CP_ASYNC16(dst, src) asm volatile("cp.async.cg.shared.global [%0], [%1], 16;" :: "r"(dst), "l"(src))
#define CP_COMMIT()          asm volatile("cp.async.commit_group;" ::: "memory")
#define CP_WAIT0()           asm volatile("cp.async.wait_group 0;" ::: "memory")

// ---------------- init / graph preprocessing ----------------
__global__ void init_kernel(float* __restrict__ out, int nrows) {
    int i = blockIdx.x * blockDim.x + threadIdx.x;
    if (i < nrows) g_cursor[i] = 0;
    if (i < FPL) out[i] = 0.f;
    if (i < FEAT) { g_bnAll[0][0][i] = 1.f; g_bnAll[1][0][i] = 0.f; }
    if (i == 0) g_mode32 = 0;
}

__global__ void probe_kernel(const s64* __restrict__ ei, int nedges, int nrows) {
    int t = threadIdx.x;
    if (t < nedges && t < 1024) {
        s64 v = ei[t];
        if (v < 0 || v >= (s64)nrows) atomicExch(&g_mode32, 1);
    }
}

__global__ void hist_kernel(const s64* __restrict__ ei, int nedges) {
    int e = blockIdx.x * blockDim.x + threadIdx.x;
    if (e >= nedges) return;
    int d = g_mode32 ? ((const int*)ei)[nedges + e] : (int)ei[nedges + e];
    atomicAdd(&g_cursor[d], 1);
}

__global__ void scanA_kernel(int n) {
    __shared__ int sred[256];
    int b = blockIdx.x, t = threadIdx.x, i = b * 256 + t;
    sred[t] = (i < n) ? g_cursor[i] : 0;
    __syncthreads();
    for (int o = 128; o > 0; o >>= 1) {
        if (t < o) sred[t] += sred[t + o];
        __syncthreads();
    }
    if (t == 0) g_bsum[b] = sred[0];
}
__global__ void scanB_kernel(int nblk, int n, int E) {
    __shared__ int ss[256];
    int t = threadIdx.x;
    int v = (t < nblk) ? g_bsum[t] : 0;
    ss[t] = v; __syncthreads();
    for (int o = 1; o < 256; o <<= 1) {
        int u = (t >= o) ? ss[t - o] : 0;
        __syncthreads(); ss[t] += u; __syncthreads();
    }
    if (t < nblk) g_bsum[t] = ss[t] - v;   // exclusive
    if (t == 0) g_rowptr[n] = E;
}
__global__ void scanC_kernel(int n) {
    __shared__ int ss[256];
    int b = blockIdx.x, t = threadIdx.x, i = b * 256 + t;
    int v = (i < n) ? g_cursor[i] : 0;
    ss[t] = v; __syncthreads();
    for (int o = 1; o < 256; o <<= 1) {
        int u = (t >= o) ? ss[t - o] : 0;
        __syncthreads(); ss[t] += u; __syncthreads();
    }
    if (i < n) {
        int p = g_bsum[b] + ss[t] - v;
        g_rowptr[i] = p;
        g_cursor[i] = p;
    }
}

__global__ void fill_kernel(const s64* __restrict__ ei, int nedges) {
    int e = blockIdx.x * blockDim.x + threadIdx.x;
    if (e >= nedges) return;
    int d, sv;
    if (g_mode32) {
        const int* p = (const int*)ei;
        sv = p[e]; d = p[nedges + e];
    } else {
        sv = (int)ei[e]; d = (int)ei[nedges + e];
    }
    int pos = atomicAdd(&g_cursor[d], 1);
    g_col[pos] = sv;
}

// ---------------- weight conversion: fp32 [K][N] -> fp16 [n][k] per chunk, x log2e ----------------
__global__ void wconv_kernel(const float* __restrict__ init_w, const float* __restrict__ soft_w) {
    __shared__ __align__(16) __half sbuf[64 * 128];
    int m = blockIdx.x >> 5, c = blockIdx.x & 31;
    const float* W = (m == 0) ? init_w : soft_w + (size_t)(m - 1) * FEAT * FPL;
    for (int i = threadIdx.x; i < 64 * 128; i += 256) {
        int nn = i & 63, k = i >> 6;
        float v = W[(size_t)k * FPL + c * 64 + nn] * LOG2E;
        sbuf[nn * 128 + k] = __float2half_rn(v);
    }
    __syncthreads();
    uint4* dst = (uint4*)(g_Wbf + ((size_t)m * 32 + c) * 16384);
    const uint4* src = (const uint4*)sbuf;
    for (int i = threadIdx.x; i < 1024; i += 256) dst[i] = src[i];
}

__global__ void bconv_kernel(const float* __restrict__ init_b, const float* __restrict__ soft_b) {
    int i = blockIdx.x * blockDim.x + threadIdx.x;
    if (i >= 5 * FPL) return;
    int m = i >> 11, j = i & 2047;
    float v = (m == 0) ? init_b[j] : soft_b[(m - 1) * FPL + j];
    g_bsc[i] = v * LOG2E;
}

// ---------------- aggregation: agg = A .* (self + sum_neigh) + B * cnt ----------------
// srcsel: 0 = Xext (atoms), 1 = g_h0, 2 = g_h1
__global__ void agg_kernel(const float* __restrict__ Xext, int srcsel, int bnslot, int nrows) {
    if (blockIdx.x == 0 && threadIdx.x < 2 * FEAT) g_stats[threadIdx.x] = 0.f;
    int w = (blockIdx.x * blockDim.x + threadIdx.x) >> 5;
    int lane = threadIdx.x & 31;
    if (w >= nrows) return;
    const float4* F = (srcsel == 0) ? (const float4*)Xext
                    : (srcsel == 1) ? (const float4*)g_h0 : (const float4*)g_h1;
    float4 A4 = ((const float4*)g_bnAll[0][bnslot])[lane];
    float4 B4 = ((const float4*)g_bnAll[1][bnslot])[lane];
    float4 a = F[(size_t)w * 32 + lane];
    int beg = g_rowptr[w], end = g_rowptr[w + 1];
    float cnt = (float)(end - beg + 1);
    for (int e = beg; e < end; e++) {
        float4 bb = __ldg(&F[(size_t)g_col[e] * 32 + lane]);
        a.x += bb.x; a.y += bb.y; a.z += bb.z; a.w += bb.w;
    }
    a.x = a.x * A4.x + B4.x * cnt;
    a.y = a.y * A4.y + B4.y * cnt;
    a.z = a.z * A4.z + B4.z * cnt;
    a.w = a.w * A4.w + B4.w * cnt;
    ((float4*)g_agg)[(size_t)w * 32 + lane] = a;
}

// ---------------- hash layer (fp32 FFMA2) ----------------
__global__ void __launch_bounds__(256, 2)
hash_kernel(const float* __restrict__ W, const float* __restrict__ bias, int dstsel, int nrows) {
    extern __shared__ float sm[];
    float* xs = sm;              // [128 k][64 r]
    float* ws = sm + FEAT * 64;  // [128 k][128 c]
    __shared__ float sstat[FEAT], ssq[FEAT];
    float* H = dstsel ? g_h1 : g_h0;
    int tid = threadIdx.x;
    int tj = tid & 15, ti = tid >> 4;
    int row0 = blockIdx.x * 64;
    if (tid < FEAT) { sstat[tid] = 0.f; ssq[tid] = 0.f; }

#pragma unroll
    for (int i = 0; i < 8; i++) {
        int idx = tid + i * 256;
        int r = idx >> 5, k4 = idx & 31;
        float4 v = make_float4(0.f, 0.f, 0.f, 0.f);
        if (row0 + r < nrows)
            v = *(const float4*)(g_agg + (size_t)(row0 + r) * FEAT + k4 * 4);
        xs[(k4 * 4 + 0) * 64 + r] = v.x;
        xs[(k4 * 4 + 1) * 64 + r] = v.y;
        xs[(k4 * 4 + 2) * 64 + r] = v.z;
        xs[(k4 * 4 + 3) * 64 + r] = v.w;
    }
#pragma unroll
    for (int i = 0; i < 16; i++) {
        int idx = tid + i * 256;
        *(float4*)(ws + idx * 4) = *(const float4*)(W + idx * 4);
    }
    __syncthreads();

    u64 acc[4][4];
#pragma unroll
    for (int r = 0; r < 4; r++)
#pragma unroll
        for (int c = 0; c < 4; c++) acc[r][c] = 0ull;

#pragma unroll 4
    for (int k = 0; k < FEAT; k++) {
        float4 xf = *(const float4*)(xs + k * 64 + ti * 4);
        ulonglong2 wa = *(const ulonglong2*)(ws + k * FEAT + tj * 8);
        ulonglong2 wb = *(const ulonglong2*)(ws + k * FEAT + tj * 8 + 4);
        u64 x0 = pk2(xf.x), x1 = pk2(xf.y), x2 = pk2(xf.z), x3 = pk2(xf.w);
        fma2(acc[0][0], x0, wa.x); fma2(acc[0][1], x0, wa.y); fma2(acc[0][2], x0, wb.x); fma2(acc[0][3], x0, wb.y);
        fma2(acc[1][0], x1, wa.x); fma2(acc[1][1], x1, wa.y); fma2(acc[1][2], x1, wb.x); fma2(acc[1][3], x1, wb.y);
        fma2(acc[2][0], x2, wa.x); fma2(acc[2][1], x2, wa.y); fma2(acc[2][2], x2, wb.x); fma2(acc[2][3], x2, wb.y);
        fma2(acc[3][0], x3, wa.x); fma2(acc[3][1], x3, wa.y); fma2(acc[3][2], x3, wb.x); fma2(acc[3][3], x3, wb.y);
    }

    int colb = tj * 8;
    float4 bv0 = *(const float4*)(bias + colb);
    float4 bv1 = *(const float4*)(bias + colb + 4);
    float bvals[8] = {bv0.x, bv0.y, bv0.z, bv0.w, bv1.x, bv1.y, bv1.z, bv1.w};
    float s[8], q[8];
#pragma unroll
    for (int j = 0; j < 8; j++) { s[j] = 0.f; q[j] = 0.f; }
#pragma unroll
    for (int rr = 0; rr < 4; rr++) {
        int row = row0 + ti * 4 + rr;
        if (row >= nrows) break;
        float hv[8];
#pragma unroll
        for (int cp = 0; cp < 4; cp++) {
            float2 f = up2(acc[rr][cp]);
            hv[2 * cp]     = fmaxf(f.x + bvals[2 * cp], 0.f);
            hv[2 * cp + 1] = fmaxf(f.y + bvals[2 * cp + 1], 0.f);
        }
        *(float4*)(H + (size_t)row * FEAT + colb)     = make_float4(hv[0], hv[1], hv[2], hv[3]);
        *(float4*)(H + (size_t)row * FEAT + colb + 4) = make_float4(hv[4], hv[5], hv[6], hv[7]);
#pragma unroll
        for (int j = 0; j < 8; j++) { s[j] += hv[j]; q[j] += hv[j] * hv[j]; }
    }
    __syncthreads();
#pragma unroll
    for (int j = 0; j < 8; j++) {
        atomicAdd(&sstat[colb + j], s[j]);
        atomicAdd(&ssq[colb + j], q[j]);
    }
    __syncthreads();
    if (tid < FEAT) {
        atomicAdd(&g_stats[tid], sstat[tid]);
        atomicAdd(&g_stats[FEAT + tid], ssq[tid]);
    }
}

__global__ void bnfinal_kernel(const float* __restrict__ gamma, const float* __restrict__ beta,
                               int nrows, int slot) {
    int c = threadIdx.x;
    float n = (float)nrows;
    float mu = g_stats[c] / n;
    float var = g_stats[FEAT + c] / n - mu * mu;
    float A = gamma[c] * rsqrtf(var + 1e-5f);
    g_bnAll[0][slot][c] = A;
    g_bnAll[1][slot][c] = beta[c] - mu * A;
}

// ---------------- HMMA softmax-GEMM: 256 rows/block (2 tiles), shared B staging ----------------
#define APITCH 136
#define ASZ (128 * APITCH * 2)        // 34816 bytes per A tile
#define BSZ (64 * APITCH * 2)         // 17408 bytes per B stage
#define SMEMB (2 * ASZ + 2 * BSZ)     // 104448 bytes

__global__ void __launch_bounds__(256, 2)
softgemm_mma_kernel(const float* __restrict__ Xext, int xsel, int bnslot, int mIdx,
                    float* __restrict__ fp, int nrows) {
    extern __shared__ __align__(16) unsigned char dsm[];
    __shared__ __align__(16) float s_bias[2][64];
    __shared__ float s_sinv[256];
    __shared__ float s_bnA[FEAT], s_bnB[FEAT];

    const float* X = (xsel == 0) ? Xext : (xsel == 1 ? g_h0 : g_h1);
    int tid = threadIdx.x;
    int lane = tid & 31;
    int w = tid >> 5;            // warp 0..7
    int wr = w * 16;             // warp row base within tile
    int row0 = blockIdx.x * 256;

    uint32_t As_u[2] = { smem_u32(dsm), smem_u32(dsm + ASZ) };
    uint32_t Bs_u[2] = { smem_u32(dsm + 2 * ASZ), smem_u32(dsm + 2 * ASZ + BSZ) };
    uint32_t bias_u = smem_u32(s_bias);

    if (tid < FEAT) { s_bnA[tid] = g_bnAll[0][bnslot][tid]; s_bnB[tid] = g_bnAll[1][bnslot][tid]; }
    __syncthreads();   // bn coefficients visible

    const unsigned char* Wbase = g_Wbf + (size_t)mIdx * 32 * 16384;
    const float* bias = g_bsc + (size_t)mIdx * FPL;

    // ---- prefetch B chunk 0 ----
    {
        const unsigned char* src = Wbase;
#pragma unroll
        for (int i = 0; i < 4; i++) {
            int idx = tid + i * 256;
            uint32_t dst = Bs_u[0] + (uint32_t)((idx >> 4) * (APITCH * 2) + (idx & 15) * 16);
            CP_ASYNC16(dst, src + idx * 16);
        }
        if (tid < 16) CP_ASYNC16(bias_u + tid * 16, (const unsigned char*)bias + tid * 16);
        CP_COMMIT();
    }

    // ---- stage A (fp16) for both tiles: thread t: row t>>1, k-half (t&1)*64 ----
#pragma unroll
    for (int tt = 0; tt < 2; tt++) {
        int r = tid >> 1, kh = (tid & 1) * 64;
        int row = row0 + tt * 128 + r;
        bool v = row < nrows;
        const float* xr = X + (size_t)row * FEAT + kh;
        __half2* arow = (__half2*)((unsigned char*)dsm + tt * ASZ + (r * APITCH + kh) * 2);
#pragma unroll 8
        for (int k = 0; k < 64; k += 2) {
            float v0 = 0.f, v1 = 0.f;
            if (v) {
                float2 xv = *(const float2*)(xr + k);
                v0 = xv.x * s_bnA[kh + k] + s_bnB[kh + k];
                v1 = xv.y * s_bnA[kh + k + 1] + s_bnB[kh + k + 1];
            }
            arow[k >> 1] = __floats2half2_rn(v0, v1);
        }
    }
    __syncthreads();   // A visible

    // ---- hoist tile0 A fragments; tile1 A address for per-chunk reload ----
    int mi = lane >> 3;
    uint32_t arow_off = (uint32_t)((wr + (mi & 1) * 8 + (lane & 7)) * (APITCH * 2) + (mi >> 1) * 16);
    uint32_t a0_base = As_u[0] + arow_off;
    uint32_t a1_base = As_u[1] + arow_off;
    uint32_t afr[8][4];
#pragma unroll
    for (int ks = 0; ks < 8; ks++)
        ldm_x4(afr[ks][0], afr[ks][1], afr[ks][2], afr[ks][3], a0_base + ks * 32);

    int b_row = (lane & 7) + ((lane >> 4) << 3);      // 0..15
    int b_koff = ((lane >> 3) & 1) * 16;
    uint32_t b_off = (uint32_t)(b_row * (APITCH * 2) + b_koff);

    int gr0 = wr + (lane >> 2);                        // row within tile
    int cq = (lane & 3) * 2;
    uint4* Et0 = g_Efrag + (size_t)(2 * blockIdx.x) * 32768;
    uint4* Et1 = Et0 + 32768;

    u64 rs[2][2] = {{0ull, 0ull}, {0ull, 0ull}};       // [tile][rowhalf] packed rowsums

    for (int c = 0; c < 32; c++) {
        int buf = c & 1;
        CP_WAIT0();
        __syncthreads();           // Bs[buf] ready; all warps done with Bs[buf^1]

        // depth-1 prefetch: chunk c+1 into the other buffer
        if (c + 1 < 32) {
            const unsigned char* src = Wbase + (size_t)(c + 1) * 16384;
#pragma unroll
            for (int i = 0; i < 4; i++) {
                int idx = tid + i * 256;
                uint32_t dst = Bs_u[buf ^ 1] + (uint32_t)((idx >> 4) * (APITCH * 2) + (idx & 15) * 16);
                CP_ASYNC16(dst, src + idx * 16);
            }
            if (tid < 16) CP_ASYNC16(bias_u + (buf ^ 1) * 256 + tid * 16,
                                     (const unsigned char*)(bias + (c + 1) * 64) + tid * 16);
        }
        CP_COMMIT();

        uint32_t bb = Bs_u[buf] + b_off;
        uint32_t acc[2][4][4];     // [tile][tp][colTileA 2 | colTileB 2]
#pragma unroll
        for (int t = 0; t < 2; t++)
#pragma unroll
            for (int tp = 0; tp < 4; tp++)
#pragma unroll
                for (int j = 0; j < 4; j++) acc[t][tp][j] = 0u;

#pragma unroll
        for (int ks = 0; ks < 8; ks++) {
            uint32_t a20, a21, a22, a23;
            ldm_x4(a20, a21, a22, a23, a1_base + ks * 32);
#pragma unroll
            for (int tp = 0; tp < 4; tp++) {
                uint32_t b0, b1, b2, b3;
                ldm_x4(b0, b1, b2, b3, bb + tp * 16 * (APITCH * 2) + ks * 32);
                mma16816h(&acc[0][tp][0], afr[ks][0], afr[ks][1], afr[ks][2], afr[ks][3], b0, b1);
                mma16816h(&acc[0][tp][2], afr[ks][0], afr[ks][1], afr[ks][2], afr[ks][3], b2, b3);
                mma16816h(&acc[1][tp][0], a20, a21, a22, a23, b0, b1);
                mma16816h(&acc[1][tp][2], a20, a21, a22, a23, b2, b3);
            }
        }

        // epilogue: both tiles
#pragma unroll
        for (int tp = 0; tp < 4; tp++) {
            u64 bpA = *(const u64*)(&s_bias[buf][2 * tp * 8 + cq]);
            u64 bpB = *(const u64*)(&s_bias[buf][(2 * tp + 1) * 8 + cq]);
#pragma unroll
            for (int t = 0; t < 2; t++) {
                float2 fA0 = __half22float2(*(__half2*)&acc[t][tp][0]);   // row gr0
                float2 fA1 = __half22float2(*(__half2*)&acc[t][tp][1]);   // row gr0+8
                float2 fB0 = __half22float2(*(__half2*)&acc[t][tp][2]);
                float2 fB1 = __half22float2(*(__half2*)&acc[t][tp][3]);
                u64 sA_rA = add2p(pack2f(fA0.x, fA0.y), bpA);
                u64 sA_rB = add2p(pack2f(fA1.x, fA1.y), bpA);
                u64 sB_rA = add2p(pack2f(fB0.x, fB0.y), bpB);
                u64 sB_rB = add2p(pack2f(fB1.x, fB1.y), bpB);
                float2 t0 = up2(sA_rA), t1 = up2(sB_rA), t2 = up2(sA_rB), t3 = up2(sB_rB);
                u64 eA_rA = fexp2x2(pack2f(fminf(t0.x, 15.5f), fminf(t0.y, 15.5f)));
                u64 eB_rA = fexp2x2(pack2f(fminf(t1.x, 15.5f), fminf(t1.y, 15.5f)));
                u64 eA_rB = fexp2x2(pack2f(fminf(t2.x, 15.5f), fminf(t2.y, 15.5f)));
                u64 eB_rB = fexp2x2(pack2f(fminf(t3.x, 15.5f), fminf(t3.y, 15.5f)));
                rs[t][0] = add2p(add2p(rs[t][0], eA_rA), eB_rA);
                rs[t][1] = add2p(add2p(rs[t][1], eA_rB), eB_rB);
                uint4 ov;
                ov.x = h2of(eA_rA); ov.y = h2of(eB_rA);
                ov.z = h2of(eA_rB); ov.w = h2of(eB_rB);
                (t ? Et1 : Et0)[((c * 8 + w) * 4 + tp) * 32 + lane] = ov;
            }
        }
    }

    // rowsums for both tiles
#pragma unroll
    for (int t = 0; t < 2; t++) {
        float2 r0f = up2(rs[t][0]), r1f = up2(rs[t][1]);
        float a = r0f.x + r0f.y;
        float b = r1f.x + r1f.y;
#pragma unroll
        for (int o = 1; o < 4; o <<= 1) {
            a += __shfl_xor_sync(0xFFFFFFFFu, a, o);
            b += __shfl_xor_sync(0xFFFFFFFFu, b, o);
        }
        if ((lane & 3) == 0) {
            int rbase = row0 + t * 128;
            s_sinv[t * 128 + gr0]     = (rbase + gr0 < nrows)     ? (1.0f / a) : 0.f;
            s_sinv[t * 128 + gr0 + 8] = (rbase + gr0 + 8 < nrows) ? (1.0f / b) : 0.f;
        }
    }
    __syncthreads();   // stores + s_sinv visible block-wide

    // ---- fused pass 2: both tiles into one column accumulator ----
    {
        int c8 = tid >> 3;                 // chunk 0..31
        int sub = tid & 7;
        int tp2 = sub >> 1, lqh = sub & 1;
        float ca[8];
#pragma unroll
        for (int j = 0; j < 8; j++) ca[j] = 0.f;
        for (int t = 0; t < 2; t++) {
            const uint4* Et = t ? Et1 : Et0;
            const float* sv = s_sinv + t * 128;
            for (int w2 = 0; w2 < 8; w2++) {
#pragma unroll 2
                for (int lr = 0; lr < 8; lr++) {
                    float inv0 = sv[w2 * 16 + lr];
                    float inv1 = sv[w2 * 16 + lr + 8];
#pragma unroll
                    for (int lql = 0; lql < 2; lql++) {
                        int lane2 = lr * 4 + 2 * lqh + lql;
                        uint4 v = Et[((c8 * 8 + w2) * 4 + tp2) * 32 + lane2];
                        const __half2* hh = (const __half2*)&v;
                        float2 f0 = __half22float2(hh[0]);
                        float2 f1 = __half22float2(hh[1]);
                        float2 f2 = __half22float2(hh[2]);
                        float2 f3 = __half22float2(hh[3]);
                        ca[lql * 4 + 0] += f0.x * inv0 + f2.x * inv1;
                        ca[lql * 4 + 1] += f0.y * inv0 + f2.y * inv1;
                        ca[lql * 4 + 2] += f1.x * inv0 + f3.x * inv1;
                        ca[lql * 4 + 3] += f1.y * inv0 + f3.y * inv1;
                    }
                }
            }
        }
        int base = c8 * 64 + 16 * tp2;
#pragma unroll
        for (int lql = 0; lql < 2; lql++) {
            int lq = 2 * lqh + lql;
            atomicAdd(&fp[base + 2 * lq],         ca[lql * 4 + 0]);
            atomicAdd(&fp[base + 2 * lq + 1],     ca[lql * 4 + 1]);
            atomicAdd(&fp[base + 8 + 2 * lq],     ca[lql * 4 + 2]);
            atomicAdd(&fp[base + 8 + 2 * lq + 1], ca[lql * 4 + 3]);
        }
    }
}

// ---------------- launch ----------------
extern "C" void kernel_launch(void* const* d_in, const int* in_sizes, int n_in,
                              void* d_out, int out_size) {
    const float* atoms  = (const float*)d_in[0];
    const s64*   ei     = (const s64*)d_in[1];
    const float* init_w = (const float*)d_in[2];
    const float* init_b = (const float*)d_in[3];
    const float* hash_w = (const float*)d_in[4];
    const float* hash_b = (const float*)d_in[5];
    const float* soft_w = (const float*)d_in[6];
    const float* soft_b = (const float*)d_in[7];
    const float* gamma  = (const float*)d_in[8];
    const float* beta   = (const float*)d_in[9];
    float* out = (float*)d_out;

    int n = in_sizes[0] / FEAT;
    int E = in_sizes[1] / 2;
    int gb64 = (n + 63) / 64;
    int gb256 = (n + 255) / 256;
    int nscan = (n + 255) / 256;

    // one-time resources (host-side only; no device allocations)
    static cudaStream_t sB = nullptr;
    static cudaEvent_t evR[5], evS[5];
    if (sB == nullptr) {
        cudaStreamCreateWithFlags(&sB, cudaStreamNonBlocking);
        for (int i = 0; i < 5; i++) {
            cudaEventCreateWithFlags(&evR[i], cudaEventDisableTiming);
            cudaEventCreateWithFlags(&evS[i], cudaEventDisableTiming);
        }
    }

    cudaFuncSetAttribute(hash_kernel, cudaFuncAttributeMaxDynamicSharedMemorySize, 98304);
    cudaFuncSetAttribute(softgemm_mma_kernel, cudaFuncAttributeMaxDynamicSharedMemorySize, SMEMB);

    // ---- stream A (default): only what softgemm0 needs, then fork early ----
    init_kernel<<<(n + 255) / 256, 256>>>(out, n);
    probe_kernel<<<1, 1024>>>(ei, E, n);
    wconv_kernel<<<5 * 32, 256>>>(init_w, soft_w);
    bconv_kernel<<<(5 * FPL + 255) / 256, 256>>>(init_b, soft_b);

    // fork: softgemm 0 on stream B (doesn't need the CSR)
    cudaEventRecord(evR[0], (cudaStream_t)0);
    cudaStreamWaitEvent(sB, evR[0], 0);
    softgemm_mma_kernel<<<gb256, 256, SMEMB, sB>>>(atoms, 0, 0, 0, out, n);
    cudaEventRecord(evS[0], sB);

    // ---- stream A: build CSR concurrent with softgemm 0 ----
    hist_kernel<<<(E + 255) / 256, 256>>>(ei, E);
    scanA_kernel<<<nscan, 256>>>(n);
    scanB_kernel<<<1, 256>>>(nscan, n, E);
    scanC_kernel<<<nscan, 256>>>(n);
    fill_kernel<<<(E + 255) / 256, 256>>>(ei, E);

    // layers i = 1..4: chain on stream A runs concurrent with softgemm_{i-1} on stream B
    for (int i = 1; i <= 4; i++) {
        int srcsel = (i == 1) ? 0 : (((i - 1) & 1) + 1);
        agg_kernel<<<(n * 32 + 255) / 256, 256>>>(atoms, srcsel, i - 1, n);
        // hash_i writes h[i&1], which softgemm_{i-2} read — fence that WAR
        if (i >= 3) cudaStreamWaitEvent((cudaStream_t)0, evS[i - 2], 0);
        hash_kernel<<<gb64, 256, 98304>>>(hash_w + (size_t)(i - 1) * FEAT * FEAT,
                                          hash_b + (size_t)(i - 1) * FEAT, i & 1, n);
        bnfinal_kernel<<<1, FEAT>>>(gamma, beta, n, i);
        cudaEventRecord(evR[i], (cudaStream_t)0);
        cudaStreamWaitEvent(sB, evR[i], 0);
        softgemm_mma_kernel<<<gb256, 256, SMEMB, sB>>>(nullptr, (i & 1) + 1, i, i, out, n);
        cudaEventRecord(evS[i], sB);
    }

    // join stream B back into the default stream
    cudaStreamWaitEvent((cudaStream_t)0, evS[4], 0);
}